// round 16
// baseline (speedup 1.0000x reference)
#include <cuda_runtime.h>
#include <cuda_fp16.h>
#include <math.h>
#include <stdint.h>

// ---------------------------------------------------------------------------
// SmallTransformerBlock via mma.sync single-pass fp16 GEMMs (sm_103 PTX).
// R16: R14 base with BM=64 CTA tiles (BN=128, warp tile 32x32, 2x4 warps) to
// cut wave-quantization tails; mma-issue-bound steady rate unchanged.
// ---------------------------------------------------------------------------

#define D_MODEL 1024
#define FF_DIM  4096
#define BATCH   4
#define SEQ     2048
#define M_TOT   (BATCH * SEQ)          // 8192
#define QKV_N   (3 * D_MODEL)          // 3072

#define BM 64
#define BN 128
#define BK 64
#define STAGES 3
#define ABUF_BYTES (64 * 128)                  // A: 64 rows x 128B
#define BBUF_BYTES (128 * 128)                 // B: 128 rows x 128B
#define STAGE_BYTES (ABUF_BYTES + BBUF_BYTES)  // 24576
#define SMEM_TOTAL  (STAGES * STAGE_BYTES)     // 73728

typedef __half h16;

// -------------------------- scratch (device globals) -----------------------
__device__ h16   g_x16   [M_TOT * D_MODEL];
__device__ h16   g_wqkvT [QKV_N * D_MODEL];
__device__ h16   g_woT   [D_MODEL * D_MODEL];
__device__ h16   g_w1T   [FF_DIM * D_MODEL];
__device__ h16   g_w2T   [D_MODEL * FF_DIM];
__device__ float g_bqkv  [QKV_N];
__device__ h16   g_qkv16 [M_TOT * QKV_N];
__device__ h16   g_vT16  [M_TOT * D_MODEL];    // [B][D, T]
__device__ h16   g_sh    [BATCH * SEQ * SEQ];  // scores fp16 -> softmax in place
__device__ h16   g_ctx16 [M_TOT * D_MODEL];
__device__ float g_x1    [M_TOT * D_MODEL];
__device__ float g_y1    [M_TOT * D_MODEL];
__device__ h16   g_y116  [M_TOT * D_MODEL];
__device__ h16   g_h16a  [M_TOT * FF_DIM];
__device__ float g_x2    [M_TOT * D_MODEL];

// ------------------------------- PTX helpers -------------------------------
__device__ __forceinline__ uint32_t smem_u32(const void* p) {
    uint32_t a;
    asm("{ .reg .u64 t; cvta.to.shared.u64 t, %1; cvt.u32.u64 %0, t; }"
        : "=r"(a) : "l"(p));
    return a;
}
__device__ __forceinline__ void cp16(uint32_t dst, const void* src) {
    asm volatile("cp.async.cg.shared.global [%0], [%1], 16;\n" :: "r"(dst), "l"(src));
}
__device__ __forceinline__ void cp_commit() {
    asm volatile("cp.async.commit_group;\n" ::: "memory");
}
template<int N> __device__ __forceinline__ void cp_wait() {
    asm volatile("cp.async.wait_group %0;\n" :: "n"(N) : "memory");
}
__device__ __forceinline__ void ldsm4(uint32_t& r0, uint32_t& r1, uint32_t& r2,
                                      uint32_t& r3, uint32_t addr) {
    asm volatile("ldmatrix.sync.aligned.m8n8.x4.shared.b16 {%0,%1,%2,%3}, [%4];\n"
                 : "=r"(r0), "=r"(r1), "=r"(r2), "=r"(r3) : "r"(addr));
}
__device__ __forceinline__ void mma16816(float* d, const uint32_t* a, const uint32_t* b) {
    asm volatile(
        "mma.sync.aligned.m16n8k16.row.col.f32.f16.f16.f32 "
        "{%0,%1,%2,%3}, {%4,%5,%6,%7}, {%8,%9}, {%0,%1,%2,%3};\n"
        : "+f"(d[0]), "+f"(d[1]), "+f"(d[2]), "+f"(d[3])
        : "r"(a[0]), "r"(a[1]), "r"(a[2]), "r"(a[3]), "r"(b[0]), "r"(b[1]));
}
__device__ __forceinline__ uint32_t pack2h(h16 a, h16 b) {
    return ((uint32_t)__half_as_ushort(b) << 16) | __half_as_ushort(a);
}

// ---------------------------------------------------------------------------
// GEMM NT fp16: C[M,N] = A16 @ B16^T (+bias)(relu)(+res), oscale on fp16 out.
// 64x128x64 tile, 8 warps (warp tile 32x32, 2x4), 3-stage pipeline,
// cp.async interleaved into the ks loop. 2 CTAs/SM.
// ---------------------------------------------------------------------------
template<bool F32OUT, bool HALFOUT, bool RELU, bool HASRES>
__global__ __launch_bounds__(256, 2) void gemm_nt(
    const h16* __restrict__ A16, const h16* __restrict__ B16,
    const float* __restrict__ bias, const float* __restrict__ Res,
    float* __restrict__ Cf, h16* __restrict__ Ch, float oscale,
    int M, int N, int K, int lda, int ldb, int ldc,
    long long aS, long long bS, long long cS)
{
    extern __shared__ char smraw[];
    const uint32_t smb = smem_u32(smraw);
    const int tid  = threadIdx.x;
    const int wid  = tid >> 5;
    const int lane = tid & 31;
    const int wm = wid & 1;            // m offset wm*32
    const int wn = wid >> 1;           // n offset wn*32
    const int quad = lane >> 3, lrow = lane & 7;
    const int bz = blockIdx.z;
    const int bm = blockIdx.y * BM;
    const int bn = blockIdx.x * BN;

    const int trow = tid >> 3;                 // 0..31
    const int lc   = tid & 7;
    const int lk   = lc * 8;
    const long long rowStepA = 32LL * lda;
    const long long rowStepB = 32LL * ldb;
    const h16* pA = A16 + (long long)bz * aS + (long long)(bm + trow) * lda + lk;
    const h16* pB = B16 + (long long)bz * bS + (long long)(bn + trow) * ldb + lk;
    const uint32_t d0 = (uint32_t)(trow * 128 + ((lc ^ (trow & 7)) * 16));

    const uint32_t bit4  = (uint32_t)(((quad >> 1) ^ (lrow & 1)) << 4);
    const uint32_t lrow6 = (uint32_t)(lrow & 6);
    uint32_t baseA[2], baseB[2];
    #pragma unroll
    for (int fm = 0; fm < 2; fm++)
        baseA[fm] = (uint32_t)((wm * 32 + fm * 16 + (quad & 1) * 8 + lrow) * 128) + bit4;
    #pragma unroll
    for (int f2 = 0; f2 < 2; f2++)
        baseB[f2] = ABUF_BYTES +
            (uint32_t)((wn * 32 + f2 * 16 + (quad & 1) * 8 + lrow) * 128) + bit4;

    float acc[2][4][4];
    #pragma unroll
    for (int i = 0; i < 2; i++)
        #pragma unroll
        for (int j = 0; j < 4; j++)
            #pragma unroll
            for (int c = 0; c < 4; c++) acc[i][j][c] = 0.0f;

    const int T = K / BK;

    // 6 chunks/thread per stage: idx 0-1 = A rows (trow + 32*idx),
    // idx 2-5 = B rows (trow + 32*(idx-2)).
    auto cp_one = [&](int idx, int k0, uint32_t stb) {
        if (idx < 2)
            cp16(stb + d0 + (uint32_t)idx * 4096,
                 pA + (long long)idx * rowStepA + k0);
        else
            cp16(stb + ABUF_BYTES + d0 + (uint32_t)(idx - 2) * 4096,
                 pB + (long long)(idx - 2) * rowStepB + k0);
    };
    auto load_stage = [&](int kt, int s) {
        const uint32_t stb = smb + (uint32_t)s * STAGE_BYTES;
        const int k0 = kt * BK;
        #pragma unroll
        for (int i = 0; i < 6; i++) cp_one(i, k0, stb);
    };

    load_stage(0, 0); cp_commit();
    load_stage(1, 1); cp_commit();

    int sCur = 0, sLd = 2;
    for (int t = 0; t < T; t++) {
        cp_wait<1>();
        __syncthreads();
        const uint32_t stb  = smb + (uint32_t)sCur * STAGE_BYTES;
        const uint32_t stbL = smb + (uint32_t)sLd * STAGE_BYTES;
        const bool doLoad = (t + 2 < T);
        const int k0n = (t + 2) * BK;

        #pragma unroll
        for (int ks = 0; ks < 4; ks++) {
            const uint32_t kk = ((uint32_t)(ks * 2) ^ lrow6) << 4;
            if (doLoad && ks < 2) cp_one(ks * 2, k0n, stbL);
            uint32_t ah[2][4];
            #pragma unroll
            for (int fm = 0; fm < 2; fm++)
                ldsm4(ah[fm][0], ah[fm][1], ah[fm][2], ah[fm][3],
                      stb + baseA[fm] + kk);
            uint32_t bf[4][2];
            #pragma unroll
            for (int f2 = 0; f2 < 2; f2++) {
                uint32_t t0, t1, t2, t3;
                ldsm4(t0, t1, t2, t3, stb + baseB[f2] + kk);
                bf[2*f2][0] = t0; bf[2*f2][1] = t2;
                bf[2*f2+1][0] = t1; bf[2*f2+1][1] = t3;
            }
            if (doLoad) {
                if (ks < 2) cp_one(ks * 2 + 1, k0n, stbL);
                else        cp_one(ks + 2,     k0n, stbL);
            }
            #pragma unroll
            for (int fm = 0; fm < 2; fm++)
                #pragma unroll
                for (int fn = 0; fn < 4; fn++)
                    mma16816(acc[fm][fn], ah[fm], bf[fn]);
        }
        cp_commit();
        sCur = (sCur == 2) ? 0 : sCur + 1;
        sLd  = (sLd  == 2) ? 0 : sLd  + 1;
    }

    // ---------------- epilogue ----------------
    const int groupID = lane >> 2, tIdx = lane & 3;
    #pragma unroll
    for (int fm = 0; fm < 2; fm++) {
        #pragma unroll
        for (int half = 0; half < 2; half++) {
            int row = bm + wm * 32 + fm * 16 + half * 8 + groupID;
            long long rbase = (long long)bz * cS + (long long)row * ldc;
            #pragma unroll
            for (int fn = 0; fn < 4; fn++) {
                int col = bn + wn * 32 + fn * 8 + tIdx * 2;
                float v0 = acc[fm][fn][half * 2 + 0];
                float v1 = acc[fm][fn][half * 2 + 1];
                if (bias) { v0 += __ldg(bias + col); v1 += __ldg(bias + col + 1); }
                if (RELU) { v0 = fmaxf(v0, 0.0f); v1 = fmaxf(v1, 0.0f); }
                if (HASRES) {
                    float2 rv = *(const float2*)(Res + rbase + col);
                    v0 += rv.x; v1 += rv.y;
                }
                if (F32OUT)
                    *(float2*)(Cf + rbase + col) = make_float2(v0, v1);
                if (HALFOUT) {
                    v0 *= oscale; v1 *= oscale;
                    *(uint32_t*)(Ch + rbase + col) =
                        pack2h(__float2half_rn(v0), __float2half_rn(v1));
                }
            }
        }
    }
}

// ---------------------------------------------------------------------------
// Elementwise quantize: fp32 -> fp16
// ---------------------------------------------------------------------------
__global__ __launch_bounds__(256) void quant_kernel(
    const float* __restrict__ src, h16* __restrict__ dst, int n4)
{
    int i = blockIdx.x * 256 + threadIdx.x;
    if (i >= n4) return;
    float4 v = ((const float4*)src)[i];
    ((uint2*)dst)[i] = make_uint2(
        pack2h(__float2half_rn(v.x), __float2half_rn(v.y)),
        pack2h(__float2half_rn(v.z), __float2half_rn(v.w)));
}

// bias concat: [bq | bk | bv]
__global__ __launch_bounds__(256) void bias_concat_kernel(
    const float* __restrict__ bq, const float* __restrict__ bk,
    const float* __restrict__ bv, float* __restrict__ dst)
{
    int i = blockIdx.x * 256 + threadIdx.x;
    if (i >= QKV_N) return;
    float v = (i < D_MODEL) ? bq[i]
            : (i < 2 * D_MODEL) ? bk[i - D_MODEL] : bv[i - 2 * D_MODEL];
    dst[i] = v;
}

// ---------------------------------------------------------------------------
// Transpose-quantize: src [R,C] fp32 -> dst [C,R] fp16.
// ---------------------------------------------------------------------------
__global__ __launch_bounds__(256) void transpose_quant_kernel(
    const float* __restrict__ src, h16* __restrict__ dstT,
    int R, int C, long long sS, long long dS)
{
    __shared__ float tile[32][33];
    const float* S = src + (long long)blockIdx.z * sS;
    int c0 = blockIdx.x * 32, r0 = blockIdx.y * 32;
    int tx = threadIdx.x & 31, ty = threadIdx.x >> 5;
    #pragma unroll
    for (int i = 0; i < 32; i += 8)
        tile[ty + i][tx] = S[(long long)(r0 + ty + i) * C + c0 + tx];
    __syncthreads();
    #pragma unroll
    for (int i = 0; i < 32; i += 8) {
        long long o = (long long)blockIdx.z * dS + (long long)(c0 + ty + i) * R + r0 + tx;
        dstT[o] = __float2half_rn(tile[tx][ty + i]);
    }
}

// fp16 strided transpose
__global__ __launch_bounds__(256) void transpose16_kernel(
    const h16* __restrict__ src, h16* __restrict__ dstT,
    int R, int ldS, long long sS, long long dS)
{
    __shared__ h16 tile[32][33];
    const h16* S = src + (long long)blockIdx.z * sS;
    int c0 = blockIdx.x * 32, r0 = blockIdx.y * 32;
    int tx = threadIdx.x & 31, ty = threadIdx.x >> 5;
    #pragma unroll
    for (int i = 0; i < 32; i += 8)
        tile[ty + i][tx] = S[(long long)(r0 + ty + i) * ldS + c0 + tx];
    __syncthreads();
    #pragma unroll
    for (int i = 0; i < 32; i += 8) {
        long long o = (long long)blockIdx.z * dS + (long long)(c0 + ty + i) * R + r0 + tx;
        dstT[o] = tile[tx][ty + i];
    }
}

// Batched: the four 1024x1024 weights in one launch.
__global__ __launch_bounds__(256) void transpose_quant4_kernel(
    const float* __restrict__ s0, const float* __restrict__ s1,
    const float* __restrict__ s2, const float* __restrict__ s3,
    h16* __restrict__ d0p, h16* __restrict__ d1p,
    h16* __restrict__ d2p, h16* __restrict__ d3p)
{
    __shared__ float tile[32][33];
    const int z = blockIdx.z;
    const float* S = (z == 0) ? s0 : (z == 1) ? s1 : (z == 2) ? s2 : s3;
    h16* D = (z == 0) ? d0p : (z == 1) ? d1p : (z == 2) ? d2p : d3p;
    int c0 = blockIdx.x * 32, r0 = blockIdx.y * 32;
    int tx = threadIdx.x & 31, ty = threadIdx.x >> 5;
    #pragma unroll
    for (int i = 0; i < 32; i += 8)
        tile[ty + i][tx] = S[(long long)(r0 + ty + i) * D_MODEL + c0 + tx];
    __syncthreads();
    #pragma unroll
    for (int i = 0; i < 32; i += 8) {
        long long o = (long long)(c0 + ty + i) * D_MODEL + r0 + tx;
        D[o] = __float2half_rn(tile[tx][ty + i]);
    }
}

// ------------------------------- reductions --------------------------------
__device__ __forceinline__ float block_sum(float v) {
    __shared__ float sh[8];
    int lane = threadIdx.x & 31, w = threadIdx.x >> 5;
    #pragma unroll
    for (int o = 16; o > 0; o >>= 1) v += __shfl_xor_sync(0xffffffffu, v, o);
    if (lane == 0) sh[w] = v;
    __syncthreads();
    if (w == 0) {
        float t = (lane < 8) ? sh[lane] : 0.0f;
        #pragma unroll
        for (int o = 4; o > 0; o >>= 1) t += __shfl_xor_sync(0xffffffffu, t, o);
        if (lane == 0) sh[0] = t;
    }
    __syncthreads();
    float r = sh[0];
    __syncthreads();
    return r;
}
__device__ __forceinline__ float block_max(float v) {
    __shared__ float sh[8];
    int lane = threadIdx.x & 31, w = threadIdx.x >> 5;
    #pragma unroll
    for (int o = 16; o > 0; o >>= 1) v = fmaxf(v, __shfl_xor_sync(0xffffffffu, v, o));
    if (lane == 0) sh[w] = v;
    __syncthreads();
    if (w == 0) {
        float t = (lane < 8) ? sh[lane] : -3.4e38f;
        #pragma unroll
        for (int o = 4; o > 0; o >>= 1) t = fmaxf(t, __shfl_xor_sync(0xffffffffu, t, o));
        if (lane == 0) sh[0] = t;
    }
    __syncthreads();
    float r = sh[0];
    __syncthreads();
    return r;
}

// ---------------------------------------------------------------------------
// In-place fp16 softmax over rows of SEQ=2048 (scores already scaled).
// ---------------------------------------------------------------------------
__global__ __launch_bounds__(256) void softmax16_kernel(h16* __restrict__ S)
{
    h16* row = S + (long long)blockIdx.x * SEQ;
    int tid = threadIdx.x;
    uint4 raw = ((const uint4*)row)[tid];
    float2 f0 = __half22float2(*(__half2*)&raw.x);
    float2 f1 = __half22float2(*(__half2*)&raw.y);
    float2 f2 = __half22float2(*(__half2*)&raw.z);
    float2 f3 = __half22float2(*(__half2*)&raw.w);

    float m = fmaxf(fmaxf(fmaxf(f0.x, f0.y), fmaxf(f1.x, f1.y)),
                    fmaxf(fmaxf(f2.x, f2.y), fmaxf(f3.x, f3.y)));
    m = block_max(m);
    f0.x = expf(f0.x - m); f0.y = expf(f0.y - m);
    f1.x = expf(f1.x - m); f1.y = expf(f1.y - m);
    f2.x = expf(f2.x - m); f2.y = expf(f2.y - m);
    f3.x = expf(f3.x - m); f3.y = expf(f3.y - m);
    float s = f0.x + f0.y + f1.x + f1.y + f2.x + f2.y + f3.x + f3.y;
    s = block_sum(s);
    float inv = 1.0f / s;

    uint4 outw;
    outw.x = pack2h(__float2half_rn(f0.x * inv), __float2half_rn(f0.y * inv));
    outw.y = pack2h(__float2half_rn(f1.x * inv), __float2half_rn(f1.y * inv));
    outw.z = pack2h(__float2half_rn(f2.x * inv), __float2half_rn(f2.y * inv));
    outw.w = pack2h(__float2half_rn(f3.x * inv), __float2half_rn(f3.y * inv));
    ((uint4*)row)[tid] = outw;
}

// ---------------------------------------------------------------------------
// LayerNorm D=1024; optional fp16 quantized emission.
// ---------------------------------------------------------------------------
template<bool EMITH>
__global__ __launch_bounds__(256) void layernorm_kernel(
    const float* __restrict__ X, const float* __restrict__ g,
    const float* __restrict__ b, float* __restrict__ Y, h16* __restrict__ Yh)
{
    const float* x = X + (long long)blockIdx.x * D_MODEL;
    int tid = threadIdx.x;
    float4 v = ((const float4*)x)[tid];
    float s = v.x + v.y + v.z + v.w;
    s = block_sum(s);
    float mean = s * (1.0f / D_MODEL);
    float dx=v.x-mean, dy=v.y-mean, dz=v.z-mean, dw=v.w-mean;
    float ss = dx*dx + dy*dy + dz*dz + dw*dw;
    ss = block_sum(ss);
    float rstd = rsqrtf(ss * (1.0f / D_MODEL) + 1e-5f);
    float4 gg = ((const float4*)g)[tid];
    float4 bb = ((const float4*)b)[tid];
    float4 o;
    o.x = dx*rstd*gg.x + bb.x;
    o.y = dy*rstd*gg.y + bb.y;
    o.z = dz*rstd*gg.z + bb.z;
    o.w = dw*rstd*gg.w + bb.w;
    long long base = (long long)blockIdx.x * D_MODEL;
    ((float4*)(Y + base))[tid] = o;
    if (EMITH) {
        ((uint2*)(Yh + base))[tid] = make_uint2(
            pack2h(__float2half_rn(o.x), __float2half_rn(o.y)),
            pack2h(__float2half_rn(o.z), __float2half_rn(o.w)));
    }
}

// ---------------------------------------------------------------------------
// Launch
// ---------------------------------------------------------------------------
extern "C" void kernel_launch(void* const* d_in, const int* in_sizes, int n_in,
                              void* d_out, int out_size)
{
    const float* x     = (const float*)d_in[0];
    const float* wq    = (const float*)d_in[1];
    const float* bq    = (const float*)d_in[2];
    const float* wk    = (const float*)d_in[3];
    const float* bk    = (const float*)d_in[4];
    const float* wv    = (const float*)d_in[5];
    const float* bv    = (const float*)d_in[6];
    const float* wo    = (const float*)d_in[7];
    const float* bo    = (const float*)d_in[8];
    const float* w1    = (const float*)d_in[9];
    const float* b1    = (const float*)d_in[10];
    const float* w2    = (const float*)d_in[11];
    const float* b2    = (const float*)d_in[12];
    const float* g1    = (const float*)d_in[13];
    const float* beta1 = (const float*)d_in[14];
    const float* g2    = (const float*)d_in[15];
    const float* beta2 = (const float*)d_in[16];
    float* out = (float*)d_out;

    #define SYM(p, s) void* p##_; cudaGetSymbolAddress(&p##_, s);
    SYM(x16, g_x16)
    SYM(wqkvT, g_wqkvT) SYM(woT, g_woT)
    SYM(w1T, g_w1T) SYM(w2T, g_w2T)
    SYM(bqkv, g_bqkv)
    SYM(qkv16, g_qkv16)
    SYM(vT16, g_vT16)
    SYM(sh, g_sh)
    SYM(c16, g_ctx16)
    SYM(x1, g_x1)   SYM(y1, g_y1)  SYM(y116, g_y116)
    SYM(hh, g_h16a)
    SYM(x2, g_x2)
    #undef SYM

    cudaFuncSetAttribute(gemm_nt<1,0,0,0>, cudaFuncAttributeMaxDynamicSharedMemorySize, SMEM_TOTAL);
    cudaFuncSetAttribute(gemm_nt<0,1,0,0>, cudaFuncAttributeMaxDynamicSharedMemorySize, SMEM_TOTAL);
    cudaFuncSetAttribute(gemm_nt<0,1,1,0>, cudaFuncAttributeMaxDynamicSharedMemorySize, SMEM_TOTAL);
    cudaFuncSetAttribute(gemm_nt<1,0,0,1>, cudaFuncAttributeMaxDynamicSharedMemorySize, SMEM_TOTAL);

    dim3 blk(256);
    h16* qkv = (h16*)qkv16_;
    const float inv_scale = 0.0883883476483184f;  // 1/sqrt(128)

    // 0. quantize x -> fp16
    quant_kernel<<<M_TOT * D_MODEL / 4 / 256, blk>>>(x, (h16*)x16_, M_TOT * D_MODEL / 4);

    // 1. transpose-quantize wq,wk,wv into wqkvT; wo into woT
    transpose_quant4_kernel<<<dim3(D_MODEL/32, D_MODEL/32, 4), blk>>>(
        wq, wk, wv, wo,
        (h16*)wqkvT_, (h16*)wqkvT_ + D_MODEL*D_MODEL,
        (h16*)wqkvT_ + 2*D_MODEL*D_MODEL, (h16*)woT_);

    // 2. concat biases
    bias_concat_kernel<<<(QKV_N + 255)/256, blk>>>(bq, bk, bv, (float*)bqkv_);

    // 3. fused QKV GEMM -> qkv16 [8192,3072]
    gemm_nt<0,1,0,0><<<dim3(QKV_N/BN, M_TOT/BM, 1), blk, SMEM_TOTAL>>>(
        (h16*)x16_, (h16*)wqkvT_, (float*)bqkv_, nullptr, nullptr, qkv, 1.0f,
        M_TOT, QKV_N, D_MODEL, D_MODEL, D_MODEL, QKV_N, 0, 0, 0);

    // 4-5. w1, w2 transposes
    transpose_quant_kernel<<<dim3(FF_DIM/32, D_MODEL/32, 1), blk>>>(
        w1, (h16*)w1T_, D_MODEL, FF_DIM, 0, 0);
    transpose_quant_kernel<<<dim3(D_MODEL/32, FF_DIM/32, 1), blk>>>(
        w2, (h16*)w2T_, FF_DIM, D_MODEL, 0, 0);

    // 6. vT per batch
    transpose16_kernel<<<dim3(D_MODEL/32, SEQ/32, BATCH), blk>>>(
        qkv + 2*D_MODEL, (h16*)vT16_, SEQ, QKV_N,
        (long long)SEQ*QKV_N, (long long)D_MODEL*SEQ);

    // 7. scores = (q @ k^T) * inv_scale, fp16 out
    gemm_nt<0,1,0,0><<<dim3(SEQ/BN, SEQ/BM, BATCH), blk, SMEM_TOTAL>>>(
        qkv, qkv + D_MODEL, nullptr, nullptr, nullptr, (h16*)sh_, inv_scale,
        SEQ, SEQ, D_MODEL, QKV_N, QKV_N, SEQ,
        (long long)SEQ*QKV_N, (long long)SEQ*QKV_N, (long long)SEQ*SEQ);

    // 8. softmax in place (fp16)
    softmax16_kernel<<<BATCH*SEQ, blk>>>((h16*)sh_);

    // 9. ctx = P @ vT^T (fp16 out)
    gemm_nt<0,1,0,0><<<dim3(D_MODEL/BN, SEQ/BM, BATCH), blk, SMEM_TOTAL>>>(
        (h16*)sh_, (h16*)vT16_, nullptr, nullptr, nullptr, (h16*)c16_, 1.0f,
        SEQ, D_MODEL, SEQ, SEQ, SEQ, D_MODEL,
        (long long)SEQ*SEQ, (long long)D_MODEL*SEQ, (long long)SEQ*D_MODEL);

    // 10. x1 = x + ctx @ wo^T + bo
    gemm_nt<1,0,0,1><<<dim3(D_MODEL/BN, M_TOT/BM, 1), blk, SMEM_TOTAL>>>(
        (h16*)c16_, (h16*)woT_, bo, x, (float*)x1_, nullptr, 1.0f,
        M_TOT, D_MODEL, D_MODEL, D_MODEL, D_MODEL, D_MODEL, 0, 0, 0);

    // 11. y1 = LN1(x1), emit fp16
    layernorm_kernel<true><<<M_TOT, blk>>>((float*)x1_, g1, beta1, (float*)y1_, (h16*)y116_);

    // 12. h = relu(y1 @ w1^T + b1) (fp16 out)
    gemm_nt<0,1,1,0><<<dim3(FF_DIM/BN, M_TOT/BM, 1), blk, SMEM_TOTAL>>>(
        (h16*)y116_, (h16*)w1T_, b1, nullptr, nullptr, (h16*)hh_, 1.0f,
        M_TOT, FF_DIM, D_MODEL, D_MODEL, D_MODEL, FF_DIM, 0, 0, 0);

    // 13. x2 = y1 + h @ w2^T + b2
    gemm_nt<1,0,0,1><<<dim3(D_MODEL/BN, M_TOT/BM, 1), blk, SMEM_TOTAL>>>(
        (h16*)hh_, (h16*)w2T_, b2, (float*)y1_, (float*)x2_, nullptr, 1.0f,
        M_TOT, D_MODEL, FF_DIM, FF_DIM, FF_DIM, D_MODEL, 0, 0, 0);

    // 14. out = LN2(x2)
    layernorm_kernel<false><<<M_TOT, blk>>>((float*)x2_, g2, beta2, out, nullptr);
}

// round 17
// speedup vs baseline: 1.0970x; 1.0970x over previous
#include <cuda_runtime.h>
#include <cuda_fp16.h>
#include <math.h>
#include <stdint.h>

// ---------------------------------------------------------------------------
// SmallTransformerBlock via mma.sync single-pass fp16 GEMMs (sm_103 PTX).
// R17 = R14 verbatim (session best: 882.75us, rel_err 5.74e-4).
// Scores GEMM emits scaled fp16, softmax in place; 128x128x64 tiles,
// 3-stage pipeline, cp.async interleaved into the ks loop, 2 CTAs/SM.
// ---------------------------------------------------------------------------

#define D_MODEL 1024
#define FF_DIM  4096
#define BATCH   4
#define SEQ     2048
#define M_TOT   (BATCH * SEQ)          // 8192
#define QKV_N   (3 * D_MODEL)          // 3072

#define BM 128
#define BN 128
#define BK 64
#define STAGES 3
#define ABUF_BYTES (128 * 128)
#define BBUF_BYTES (128 * 128)
#define STAGE_BYTES (ABUF_BYTES + BBUF_BYTES)  // 32768
#define SMEM_TOTAL  (STAGES * STAGE_BYTES)     // 98304

typedef __half h16;

// -------------------------- scratch (device globals) -----------------------
__device__ h16   g_x16   [M_TOT * D_MODEL];
__device__ h16   g_wqkvT [QKV_N * D_MODEL];
__device__ h16   g_woT   [D_MODEL * D_MODEL];
__device__ h16   g_w1T   [FF_DIM * D_MODEL];
__device__ h16   g_w2T   [D_MODEL * FF_DIM];
__device__ float g_bqkv  [QKV_N];
__device__ h16   g_qkv16 [M_TOT * QKV_N];
__device__ h16   g_vT16  [M_TOT * D_MODEL];    // [B][D, T]
__device__ h16   g_sh    [BATCH * SEQ * SEQ];  // scores fp16 -> softmax in place
__device__ h16   g_ctx16 [M_TOT * D_MODEL];
__device__ float g_x1    [M_TOT * D_MODEL];
__device__ float g_y1    [M_TOT * D_MODEL];
__device__ h16   g_y116  [M_TOT * D_MODEL];
__device__ h16   g_h16a  [M_TOT * FF_DIM];
__device__ float g_x2    [M_TOT * D_MODEL];

// ------------------------------- PTX helpers -------------------------------
__device__ __forceinline__ uint32_t smem_u32(const void* p) {
    uint32_t a;
    asm("{ .reg .u64 t; cvta.to.shared.u64 t, %1; cvt.u32.u64 %0, t; }"
        : "=r"(a) : "l"(p));
    return a;
}
__device__ __forceinline__ void cp16(uint32_t dst, const void* src) {
    asm volatile("cp.async.cg.shared.global [%0], [%1], 16;\n" :: "r"(dst), "l"(src));
}
__device__ __forceinline__ void cp_commit() {
    asm volatile("cp.async.commit_group;\n" ::: "memory");
}
template<int N> __device__ __forceinline__ void cp_wait() {
    asm volatile("cp.async.wait_group %0;\n" :: "n"(N) : "memory");
}
__device__ __forceinline__ void ldsm4(uint32_t& r0, uint32_t& r1, uint32_t& r2,
                                      uint32_t& r3, uint32_t addr) {
    asm volatile("ldmatrix.sync.aligned.m8n8.x4.shared.b16 {%0,%1,%2,%3}, [%4];\n"
                 : "=r"(r0), "=r"(r1), "=r"(r2), "=r"(r3) : "r"(addr));
}
__device__ __forceinline__ void mma16816(float* d, const uint32_t* a, const uint32_t* b) {
    asm volatile(
        "mma.sync.aligned.m16n8k16.row.col.f32.f16.f16.f32 "
        "{%0,%1,%2,%3}, {%4,%5,%6,%7}, {%8,%9}, {%0,%1,%2,%3};\n"
        : "+f"(d[0]), "+f"(d[1]), "+f"(d[2]), "+f"(d[3])
        : "r"(a[0]), "r"(a[1]), "r"(a[2]), "r"(a[3]), "r"(b[0]), "r"(b[1]));
}
__device__ __forceinline__ uint32_t pack2h(h16 a, h16 b) {
    return ((uint32_t)__half_as_ushort(b) << 16) | __half_as_ushort(a);
}

// ---------------------------------------------------------------------------
// GEMM NT fp16: C[M,N] = A16 @ B16^T (+bias)(relu)(+res), strided operands.
// oscale applied before HALFOUT pack (used to fold attention 1/scale).
// 128x128x64 tile, 8 warps, 3-stage pipeline, cp.async interleaved, occ 2.
// ---------------------------------------------------------------------------
template<bool F32OUT, bool HALFOUT, bool RELU, bool HASRES>
__global__ __launch_bounds__(256, 2) void gemm_nt(
    const h16* __restrict__ A16, const h16* __restrict__ B16,
    const float* __restrict__ bias, const float* __restrict__ Res,
    float* __restrict__ Cf, h16* __restrict__ Ch, float oscale,
    int M, int N, int K, int lda, int ldb, int ldc,
    long long aS, long long bS, long long cS)
{
    extern __shared__ char smraw[];
    const uint32_t smb = smem_u32(smraw);
    const int tid  = threadIdx.x;
    const int wid  = tid >> 5;
    const int lane = tid & 31;
    const int wm = wid & 3;
    const int wn = wid >> 2;
    const int quad = lane >> 3, lrow = lane & 7;
    const int bz = blockIdx.z;
    const int bm = blockIdx.y * BM;
    const int bn = blockIdx.x * BN;

    const int trow = tid >> 3;
    const int lc   = tid & 7;
    const int lk   = lc * 8;
    const long long rowStepA = 32LL * lda;
    const long long rowStepB = 32LL * ldb;
    const h16* pA = A16 + (long long)bz * aS + (long long)(bm + trow) * lda + lk;
    const h16* pB = B16 + (long long)bz * bS + (long long)(bn + trow) * ldb + lk;
    const uint32_t d0 = (uint32_t)(trow * 128 + ((lc ^ (trow & 7)) * 16));

    const uint32_t bit4  = (uint32_t)(((quad >> 1) ^ (lrow & 1)) << 4);
    const uint32_t lrow6 = (uint32_t)(lrow & 6);
    uint32_t baseA[2], baseB[4];
    #pragma unroll
    for (int fm = 0; fm < 2; fm++)
        baseA[fm] = (uint32_t)((wm * 32 + fm * 16 + (quad & 1) * 8 + lrow) * 128) + bit4;
    #pragma unroll
    for (int f2 = 0; f2 < 4; f2++)
        baseB[f2] = ABUF_BYTES +
            (uint32_t)((wn * 64 + f2 * 16 + (quad & 1) * 8 + lrow) * 128) + bit4;

    float acc[2][8][4];
    #pragma unroll
    for (int i = 0; i < 2; i++)
        #pragma unroll
        for (int j = 0; j < 8; j++)
            #pragma unroll
            for (int c = 0; c < 4; c++) acc[i][j][c] = 0.0f;

    const int T = K / BK;

    auto cp_one = [&](int idx, int k0, uint32_t stb) {
        if (idx < 4)
            cp16(stb + d0 + (uint32_t)idx * 4096, pA + (long long)idx * rowStepA + k0);
        else
            cp16(stb + ABUF_BYTES + d0 + (uint32_t)(idx - 4) * 4096,
                 pB + (long long)(idx - 4) * rowStepB + k0);
    };
    auto load_stage = [&](int kt, int s) {
        const uint32_t stb = smb + (uint32_t)s * STAGE_BYTES;
        const int k0 = kt * BK;
        #pragma unroll
        for (int i = 0; i < 8; i++) cp_one(i, k0, stb);
    };

    load_stage(0, 0); cp_commit();
    load_stage(1, 1); cp_commit();

    int sCur = 0, sLd = 2;
    for (int t = 0; t < T; t++) {
        cp_wait<1>();
        __syncthreads();
        const uint32_t stb  = smb + (uint32_t)sCur * STAGE_BYTES;
        const uint32_t stbL = smb + (uint32_t)sLd * STAGE_BYTES;
        const bool doLoad = (t + 2 < T);
        const int k0n = (t + 2) * BK;

        #pragma unroll
        for (int ks = 0; ks < 4; ks++) {
            const uint32_t kk = ((uint32_t)(ks * 2) ^ lrow6) << 4;
            if (doLoad) cp_one(ks * 2, k0n, stbL);
            uint32_t ah[2][4];
            #pragma unroll
            for (int fm = 0; fm < 2; fm++)
                ldsm4(ah[fm][0], ah[fm][1], ah[fm][2], ah[fm][3],
                      stb + baseA[fm] + kk);
            uint32_t bf[8][2];
            #pragma unroll
            for (int f2 = 0; f2 < 4; f2++) {
                uint32_t t0, t1, t2, t3;
                ldsm4(t0, t1, t2, t3, stb + baseB[f2] + kk);
                bf[2*f2][0] = t0; bf[2*f2][1] = t2;
                bf[2*f2+1][0] = t1; bf[2*f2+1][1] = t3;
            }
            if (doLoad) cp_one(ks * 2 + 1, k0n, stbL);
            #pragma unroll
            for (int fm = 0; fm < 2; fm++)
                #pragma unroll
                for (int fn = 0; fn < 8; fn++)
                    mma16816(acc[fm][fn], ah[fm], bf[fn]);
        }
        cp_commit();
        sCur = (sCur == 2) ? 0 : sCur + 1;
        sLd  = (sLd  == 2) ? 0 : sLd  + 1;
    }

    // ---------------- epilogue ----------------
    const int groupID = lane >> 2, tIdx = lane & 3;
    #pragma unroll
    for (int fm = 0; fm < 2; fm++) {
        #pragma unroll
        for (int half = 0; half < 2; half++) {
            int row = bm + wm * 32 + fm * 16 + half * 8 + groupID;
            long long rbase = (long long)bz * cS + (long long)row * ldc;
            #pragma unroll
            for (int fn = 0; fn < 8; fn++) {
                int col = bn + wn * 64 + fn * 8 + tIdx * 2;
                float v0 = acc[fm][fn][half * 2 + 0];
                float v1 = acc[fm][fn][half * 2 + 1];
                if (bias) { v0 += __ldg(bias + col); v1 += __ldg(bias + col + 1); }
                if (RELU) { v0 = fmaxf(v0, 0.0f); v1 = fmaxf(v1, 0.0f); }
                if (HASRES) {
                    float2 rv = *(const float2*)(Res + rbase + col);
                    v0 += rv.x; v1 += rv.y;
                }
                if (F32OUT)
                    *(float2*)(Cf + rbase + col) = make_float2(v0, v1);
                if (HALFOUT) {
                    v0 *= oscale; v1 *= oscale;
                    *(uint32_t*)(Ch + rbase + col) =
                        pack2h(__float2half_rn(v0), __float2half_rn(v1));
                }
            }
        }
    }
}

// ---------------------------------------------------------------------------
// Elementwise quantize: fp32 -> fp16
// ---------------------------------------------------------------------------
__global__ __launch_bounds__(256) void quant_kernel(
    const float* __restrict__ src, h16* __restrict__ dst, int n4)
{
    int i = blockIdx.x * 256 + threadIdx.x;
    if (i >= n4) return;
    float4 v = ((const float4*)src)[i];
    ((uint2*)dst)[i] = make_uint2(
        pack2h(__float2half_rn(v.x), __float2half_rn(v.y)),
        pack2h(__float2half_rn(v.z), __float2half_rn(v.w)));
}

// bias concat: [bq | bk | bv]
__global__ __launch_bounds__(256) void bias_concat_kernel(
    const float* __restrict__ bq, const float* __restrict__ bk,
    const float* __restrict__ bv, float* __restrict__ dst)
{
    int i = blockIdx.x * 256 + threadIdx.x;
    if (i >= QKV_N) return;
    float v = (i < D_MODEL) ? bq[i]
            : (i < 2 * D_MODEL) ? bk[i - D_MODEL] : bv[i - 2 * D_MODEL];
    dst[i] = v;
}

// ---------------------------------------------------------------------------
// Transpose-quantize: src [R,C] fp32 -> dst [C,R] fp16.
// ---------------------------------------------------------------------------
__global__ __launch_bounds__(256) void transpose_quant_kernel(
    const float* __restrict__ src, h16* __restrict__ dstT,
    int R, int C, long long sS, long long dS)
{
    __shared__ float tile[32][33];
    const float* S = src + (long long)blockIdx.z * sS;
    int c0 = blockIdx.x * 32, r0 = blockIdx.y * 32;
    int tx = threadIdx.x & 31, ty = threadIdx.x >> 5;
    #pragma unroll
    for (int i = 0; i < 32; i += 8)
        tile[ty + i][tx] = S[(long long)(r0 + ty + i) * C + c0 + tx];
    __syncthreads();
    #pragma unroll
    for (int i = 0; i < 32; i += 8) {
        long long o = (long long)blockIdx.z * dS + (long long)(c0 + ty + i) * R + r0 + tx;
        dstT[o] = __float2half_rn(tile[tx][ty + i]);
    }
}

// fp16 strided transpose: src [R rows, stride ldS] -> dst [C, R]
__global__ __launch_bounds__(256) void transpose16_kernel(
    const h16* __restrict__ src, h16* __restrict__ dstT,
    int R, int ldS, long long sS, long long dS)
{
    __shared__ h16 tile[32][33];
    const h16* S = src + (long long)blockIdx.z * sS;
    int c0 = blockIdx.x * 32, r0 = blockIdx.y * 32;
    int tx = threadIdx.x & 31, ty = threadIdx.x >> 5;
    #pragma unroll
    for (int i = 0; i < 32; i += 8)
        tile[ty + i][tx] = S[(long long)(r0 + ty + i) * ldS + c0 + tx];
    __syncthreads();
    #pragma unroll
    for (int i = 0; i < 32; i += 8) {
        long long o = (long long)blockIdx.z * dS + (long long)(c0 + ty + i) * R + r0 + tx;
        dstT[o] = tile[tx][ty + i];
    }
}

// Batched: the four 1024x1024 weights in one launch.
__global__ __launch_bounds__(256) void transpose_quant4_kernel(
    const float* __restrict__ s0, const float* __restrict__ s1,
    const float* __restrict__ s2, const float* __restrict__ s3,
    h16* __restrict__ d0p, h16* __restrict__ d1p,
    h16* __restrict__ d2p, h16* __restrict__ d3p)
{
    __shared__ float tile[32][33];
    const int z = blockIdx.z;
    const float* S = (z == 0) ? s0 : (z == 1) ? s1 : (z == 2) ? s2 : s3;
    h16* D = (z == 0) ? d0p : (z == 1) ? d1p : (z == 2) ? d2p : d3p;
    int c0 = blockIdx.x * 32, r0 = blockIdx.y * 32;
    int tx = threadIdx.x & 31, ty = threadIdx.x >> 5;
    #pragma unroll
    for (int i = 0; i < 32; i += 8)
        tile[ty + i][tx] = S[(long long)(r0 + ty + i) * D_MODEL + c0 + tx];
    __syncthreads();
    #pragma unroll
    for (int i = 0; i < 32; i += 8) {
        long long o = (long long)(c0 + ty + i) * D_MODEL + r0 + tx;
        D[o] = __float2half_rn(tile[tx][ty + i]);
    }
}

// ------------------------------- reductions --------------------------------
__device__ __forceinline__ float block_sum(float v) {
    __shared__ float sh[8];
    int lane = threadIdx.x & 31, w = threadIdx.x >> 5;
    #pragma unroll
    for (int o = 16; o > 0; o >>= 1) v += __shfl_xor_sync(0xffffffffu, v, o);
    if (lane == 0) sh[w] = v;
    __syncthreads();
    if (w == 0) {
        float t = (lane < 8) ? sh[lane] : 0.0f;
        #pragma unroll
        for (int o = 4; o > 0; o >>= 1) t += __shfl_xor_sync(0xffffffffu, t, o);
        if (lane == 0) sh[0] = t;
    }
    __syncthreads();
    float r = sh[0];
    __syncthreads();
    return r;
}
__device__ __forceinline__ float block_max(float v) {
    __shared__ float sh[8];
    int lane = threadIdx.x & 31, w = threadIdx.x >> 5;
    #pragma unroll
    for (int o = 16; o > 0; o >>= 1) v = fmaxf(v, __shfl_xor_sync(0xffffffffu, v, o));
    if (lane == 0) sh[w] = v;
    __syncthreads();
    if (w == 0) {
        float t = (lane < 8) ? sh[lane] : -3.4e38f;
        #pragma unroll
        for (int o = 4; o > 0; o >>= 1) t = fmaxf(t, __shfl_xor_sync(0xffffffffu, t, o));
        if (lane == 0) sh[0] = t;
    }
    __syncthreads();
    float r = sh[0];
    __syncthreads();
    return r;
}

// ---------------------------------------------------------------------------
// In-place fp16 softmax over rows of SEQ=2048 (scores already scaled).
// One uint4 (8 halves) per thread.
// ---------------------------------------------------------------------------
__global__ __launch_bounds__(256) void softmax16_kernel(h16* __restrict__ S)
{
    h16* row = S + (long long)blockIdx.x * SEQ;
    int tid = threadIdx.x;
    uint4 raw = ((const uint4*)row)[tid];
    float2 f0 = __half22float2(*(__half2*)&raw.x);
    float2 f1 = __half22float2(*(__half2*)&raw.y);
    float2 f2 = __half22float2(*(__half2*)&raw.z);
    float2 f3 = __half22float2(*(__half2*)&raw.w);

    float m = fmaxf(fmaxf(fmaxf(f0.x, f0.y), fmaxf(f1.x, f1.y)),
                    fmaxf(fmaxf(f2.x, f2.y), fmaxf(f3.x, f3.y)));
    m = block_max(m);
    f0.x = expf(f0.x - m); f0.y = expf(f0.y - m);
    f1.x = expf(f1.x - m); f1.y = expf(f1.y - m);
    f2.x = expf(f2.x - m); f2.y = expf(f2.y - m);
    f3.x = expf(f3.x - m); f3.y = expf(f3.y - m);
    float s = f0.x + f0.y + f1.x + f1.y + f2.x + f2.y + f3.x + f3.y;
    s = block_sum(s);
    float inv = 1.0f / s;

    uint4 outw;
    outw.x = pack2h(__float2half_rn(f0.x * inv), __float2half_rn(f0.y * inv));
    outw.y = pack2h(__float2half_rn(f1.x * inv), __float2half_rn(f1.y * inv));
    outw.z = pack2h(__float2half_rn(f2.x * inv), __float2half_rn(f2.y * inv));
    outw.w = pack2h(__float2half_rn(f3.x * inv), __float2half_rn(f3.y * inv));
    ((uint4*)row)[tid] = outw;
}

// ---------------------------------------------------------------------------
// LayerNorm D=1024; optional fp16 quantized emission.
// ---------------------------------------------------------------------------
template<bool EMITH>
__global__ __launch_bounds__(256) void layernorm_kernel(
    const float* __restrict__ X, const float* __restrict__ g,
    const float* __restrict__ b, float* __restrict__ Y, h16* __restrict__ Yh)
{
    const float* x = X + (long long)blockIdx.x * D_MODEL;
    int tid = threadIdx.x;
    float4 v = ((const float4*)x)[tid];
    float s = v.x + v.y + v.z + v.w;
    s = block_sum(s);
    float mean = s * (1.0f / D_MODEL);
    float dx=v.x-mean, dy=v.y-mean, dz=v.z-mean, dw=v.w-mean;
    float ss = dx*dx + dy*dy + dz*dz + dw*dw;
    ss = block_sum(ss);
    float rstd = rsqrtf(ss * (1.0f / D_MODEL) + 1e-5f);
    float4 gg = ((const float4*)g)[tid];
    float4 bb = ((const float4*)b)[tid];
    float4 o;
    o.x = dx*rstd*gg.x + bb.x;
    o.y = dy*rstd*gg.y + bb.y;
    o.z = dz*rstd*gg.z + bb.z;
    o.w = dw*rstd*gg.w + bb.w;
    long long base = (long long)blockIdx.x * D_MODEL;
    ((float4*)(Y + base))[tid] = o;
    if (EMITH) {
        ((uint2*)(Yh + base))[tid] = make_uint2(
            pack2h(__float2half_rn(o.x), __float2half_rn(o.y)),
            pack2h(__float2half_rn(o.z), __float2half_rn(o.w)));
    }
}

// ---------------------------------------------------------------------------
// Launch
// ---------------------------------------------------------------------------
extern "C" void kernel_launch(void* const* d_in, const int* in_sizes, int n_in,
                              void* d_out, int out_size)
{
    const float* x     = (const float*)d_in[0];
    const float* wq    = (const float*)d_in[1];
    const float* bq    = (const float*)d_in[2];
    const float* wk    = (const float*)d_in[3];
    const float* bk    = (const float*)d_in[4];
    const float* wv    = (const float*)d_in[5];
    const float* bv    = (const float*)d_in[6];
    const float* wo    = (const float*)d_in[7];
    const float* bo    = (const float*)d_in[8];
    const float* w1    = (const float*)d_in[9];
    const float* b1    = (const float*)d_in[10];
    const float* w2    = (const float*)d_in[11];
    const float* b2    = (const float*)d_in[12];
    const float* g1    = (const float*)d_in[13];
    const float* beta1 = (const float*)d_in[14];
    const float* g2    = (const float*)d_in[15];
    const float* beta2 = (const float*)d_in[16];
    float* out = (float*)d_out;

    #define SYM(p, s) void* p##_; cudaGetSymbolAddress(&p##_, s);
    SYM(x16, g_x16)
    SYM(wqkvT, g_wqkvT) SYM(woT, g_woT)
    SYM(w1T, g_w1T) SYM(w2T, g_w2T)
    SYM(bqkv, g_bqkv)
    SYM(qkv16, g_qkv16)
    SYM(vT16, g_vT16)
    SYM(sh, g_sh)
    SYM(c16, g_ctx16)
    SYM(x1, g_x1)   SYM(y1, g_y1)  SYM(y116, g_y116)
    SYM(hh, g_h16a)
    SYM(x2, g_x2)
    #undef SYM

    cudaFuncSetAttribute(gemm_nt<1,0,0,0>, cudaFuncAttributeMaxDynamicSharedMemorySize, SMEM_TOTAL);
    cudaFuncSetAttribute(gemm_nt<0,1,0,0>, cudaFuncAttributeMaxDynamicSharedMemorySize, SMEM_TOTAL);
    cudaFuncSetAttribute(gemm_nt<0,1,1,0>, cudaFuncAttributeMaxDynamicSharedMemorySize, SMEM_TOTAL);
    cudaFuncSetAttribute(gemm_nt<1,0,0,1>, cudaFuncAttributeMaxDynamicSharedMemorySize, SMEM_TOTAL);

    dim3 blk(256);
    h16* qkv = (h16*)qkv16_;
    const float inv_scale = 0.0883883476483184f;  // 1/sqrt(128)

    // 0. quantize x -> fp16
    quant_kernel<<<M_TOT * D_MODEL / 4 / 256, blk>>>(x, (h16*)x16_, M_TOT * D_MODEL / 4);

    // 1. transpose-quantize wq,wk,wv into wqkvT; wo into woT
    transpose_quant4_kernel<<<dim3(D_MODEL/32, D_MODEL/32, 4), blk>>>(
        wq, wk, wv, wo,
        (h16*)wqkvT_, (h16*)wqkvT_ + D_MODEL*D_MODEL,
        (h16*)wqkvT_ + 2*D_MODEL*D_MODEL, (h16*)woT_);

    // 2. concat biases
    bias_concat_kernel<<<(QKV_N + 255)/256, blk>>>(bq, bk, bv, (float*)bqkv_);

    // 3. fused QKV GEMM -> qkv16 [8192,3072]
    gemm_nt<0,1,0,0><<<dim3(QKV_N/BN, M_TOT/BM, 1), blk, SMEM_TOTAL>>>(
        (h16*)x16_, (h16*)wqkvT_, (float*)bqkv_, nullptr, nullptr, qkv, 1.0f,
        M_TOT, QKV_N, D_MODEL, D_MODEL, D_MODEL, QKV_N, 0, 0, 0);

    // 4-5. w1, w2 transposes
    transpose_quant_kernel<<<dim3(FF_DIM/32, D_MODEL/32, 1), blk>>>(
        w1, (h16*)w1T_, D_MODEL, FF_DIM, 0, 0);
    transpose_quant_kernel<<<dim3(D_MODEL/32, FF_DIM/32, 1), blk>>>(
        w2, (h16*)w2T_, FF_DIM, D_MODEL, 0, 0);

    // 6. vT per batch
    transpose16_kernel<<<dim3(D_MODEL/32, SEQ/32, BATCH), blk>>>(
        qkv + 2*D_MODEL, (h16*)vT16_, SEQ, QKV_N,
        (long long)SEQ*QKV_N, (long long)D_MODEL*SEQ);

    // 7. scores = (q @ k^T) * inv_scale, fp16 out
    gemm_nt<0,1,0,0><<<dim3(SEQ/BN, SEQ/BM, BATCH), blk, SMEM_TOTAL>>>(
        qkv, qkv + D_MODEL, nullptr, nullptr, nullptr, (h16*)sh_, inv_scale,
        SEQ, SEQ, D_MODEL, QKV_N, QKV_N, SEQ,
        (long long)SEQ*QKV_N, (long long)SEQ*QKV_N, (long long)SEQ*SEQ);

    // 8. softmax in place (fp16)
    softmax16_kernel<<<BATCH*SEQ, blk>>>((h16*)sh_);

    // 9. ctx = P @ vT^T (fp16 out)
    gemm_nt<0,1,0,0><<<dim3(D_MODEL/BN, SEQ/BM, BATCH), blk, SMEM_TOTAL>>>(
        (h16*)sh_, (h16*)vT16_, nullptr, nullptr, nullptr, (h16*)c16_, 1.0f,
        SEQ, D_MODEL, SEQ, SEQ, SEQ, D_MODEL,
        (long long)SEQ*SEQ, (long long)D_MODEL*SEQ, (long long)SEQ*D_MODEL);

    // 10. x1 = x + ctx @ wo^T + bo
    gemm_nt<1,0,0,1><<<dim3(D_MODEL/BN, M_TOT/BM, 1), blk, SMEM_TOTAL>>>(
        (h16*)c16_, (h16*)woT_, bo, x, (float*)x1_, nullptr, 1.0f,
        M_TOT, D_MODEL, D_MODEL, D_MODEL, D_MODEL, D_MODEL, 0, 0, 0);

    // 11. y1 = LN1(x1), emit fp16
    layernorm_kernel<true><<<M_TOT, blk>>>((float*)x1_, g1, beta1, (float*)y1_, (h16*)y116_);

    // 12. h = relu(y1 @ w1^T + b1) (fp16 out)
    gemm_nt<0,1,1,0><<<dim3(FF_DIM/BN, M_TOT/BM, 1), blk, SMEM_TOTAL>>>(
        (h16*)y116_, (h16*)w1T_, b1, nullptr, nullptr, (h16*)hh_, 1.0f,
        M_TOT, FF_DIM, D_MODEL, D_MODEL, D_MODEL, FF_DIM, 0, 0, 0);

    // 13. x2 = y1 + h @ w2^T + b2
    gemm_nt<1,0,0,1><<<dim3(D_MODEL/BN, M_TOT/BM, 1), blk, SMEM_TOTAL>>>(
        (h16*)hh_, (h16*)w2T_, b2, (float*)y1_, (float*)x2_, nullptr, 1.0f,
        M_TOT, D_MODEL, FF_DIM, FF_DIM, FF_DIM, D_MODEL, 0, 0, 0);

    // 14. out = LN2(x2)
    layernorm_kernel<false><<<M_TOT, blk>>>((float*)x2_, g2, beta2, out, nullptr);
}